// round 9
// baseline (speedup 1.0000x reference)
#include <cuda_runtime.h>
#include <cuda_fp16.h>

// Problem constants (fixed by the dataset)
#define HH   512
#define WW   1024
#define HOo  512
#define WOo  1024
#define NPIX (HH * WW)          // 524288 input pixels
#define NOUT (HOo * WOo)        // 524288 output cells per plane
#define NPLANE 128              // B*C
#define TCX  16                 // tile cells in x
#define TCY  2                  // tile cells in y
#define TILES_X (WOo / TCX)     // 64
#define CAP  96                 // staged-entry capacity (mean ~51, 6+ sigma)

// ---- static device scratch ----
__device__ __half g_xt[(size_t)NPIX * NPLANE]; // 128MB transposed x [pixel][plane], fp16
__device__ int    g_count[NOUT];
__device__ int    g_off[NOUT];                 // per-row-local exclusive scan
__device__ int    g_cursor[NOUT];
__device__ int    g_bsum[512];
__device__ int    g_bbase[512];                // per-row global base
__device__ int4   g_entry[NPIX];               // {anchor_x, pixel, wx_bits, wy_bits}

// ---------------------------------------------------------------
// K1: transpose x [128][NPIX] fp32 -> g_xt [NPIX][128] fp16
__global__ __launch_bounds__(256)
void transpose_k(const float* __restrict__ x) {
    __shared__ float tile[32][33];
    int p0 = blockIdx.x * 32;
    int c0 = blockIdx.y * 32;
    int tx = threadIdx.x, ty = threadIdx.y;   // block (32,8)
    #pragma unroll
    for (int i = ty; i < 32; i += 8)
        tile[i][tx] = x[(size_t)(c0 + i) * NPIX + p0 + tx];
    __syncthreads();
    #pragma unroll
    for (int i = ty; i < 32; i += 8)
        g_xt[(size_t)(p0 + i) * NPLANE + c0 + tx] = __float2half(tile[tx][i]);
}

// K2: clear counters
__global__ __launch_bounds__(256)
void clear_k() {
    int i = blockIdx.x * blockDim.x + threadIdx.x;
    if (i < NOUT) g_count[i] = 0;
}

// K3: histogram — one entry per pixel, binned by anchor (floor) cell.
__global__ __launch_bounds__(256)
void hist_k(const float2* __restrict__ smap) {
    int p = blockIdx.x * blockDim.x + threadIdx.x;
    if (p >= NPIX) return;
    float2 s = __ldg(&smap[p]);
    int x0 = (int)floorf(s.x);
    int y0 = (int)floorf(s.y);
    atomicAdd(&g_count[(y0 << 10) + x0], 1);
}

// K4a: per-1024-block (= one output row) exclusive scan; totals to g_bsum
__global__ __launch_bounds__(1024)
void scanA_k() {
    int tid = threadIdx.x;
    int cell = blockIdx.x * 1024 + tid;
    int cnt = g_count[cell];
    int lane = tid & 31, wid = tid >> 5;
    int v = cnt;
    #pragma unroll
    for (int d = 1; d < 32; d <<= 1) {
        int t = __shfl_up_sync(0xFFFFFFFFu, v, d);
        if (lane >= d) v += t;
    }
    __shared__ int wsum[32];
    if (lane == 31) wsum[wid] = v;
    __syncthreads();
    if (wid == 0) {
        int s = wsum[lane];
        #pragma unroll
        for (int d = 1; d < 32; d <<= 1) {
            int t = __shfl_up_sync(0xFFFFFFFFu, s, d);
            if (lane >= d) s += t;
        }
        wsum[lane] = s;
    }
    __syncthreads();
    int excl = v - cnt + (wid ? wsum[wid - 1] : 0);
    g_off[cell] = excl;
    g_cursor[cell] = excl;
    if (tid == 1023) g_bsum[blockIdx.x] = excl + cnt;
}

// K4b: scan the 512 row totals (single block) -> g_bbase
__global__ __launch_bounds__(512)
void scanB_k() {
    int tid = threadIdx.x;
    int lane = tid & 31, wid = tid >> 5;
    int v = g_bsum[tid];
    int x = v;
    #pragma unroll
    for (int d = 1; d < 32; d <<= 1) {
        int t = __shfl_up_sync(0xFFFFFFFFu, x, d);
        if (lane >= d) x += t;
    }
    __shared__ int ws[16];
    if (lane == 31) ws[wid] = x;
    __syncthreads();
    if (wid == 0) {
        int s = (lane < 16) ? ws[lane] : 0;
        #pragma unroll
        for (int d = 1; d < 16; d <<= 1) {
            int t = __shfl_up_sync(0xFFFFFFFFu, s, d);
            if (lane >= d) s += t;
        }
        if (lane < 16) ws[lane] = s;
    }
    __syncthreads();
    g_bbase[tid] = x - v + (wid ? ws[wid - 1] : 0);
}

// K5: scatter one entry per pixel; global position = row-local cursor + row base
__global__ __launch_bounds__(256)
void scatter_k(const float2* __restrict__ smap) {
    int p = blockIdx.x * blockDim.x + threadIdx.x;
    if (p >= NPIX) return;
    float2 s = __ldg(&smap[p]);
    float x0f = floorf(s.x), y0f = floorf(s.y);
    int x0 = (int)x0f, y0 = (int)y0f;
    float wx = s.x - x0f, wy = s.y - y0f;
    int pos = atomicAdd(&g_cursor[(y0 << 10) + x0], 1) + __ldg(&g_bbase[y0]);
    g_entry[pos] = make_int4(x0, p, __float_as_int(wx), __float_as_int(wy));
}

// K6: block-staged gather. Tile = 16x2 cells. Phase 1 stages all ~51
// contributor entries + their fp16 rows into shared (batched, coalesced,
// latency-insensitive). Phase 2: each warp accumulates its 4 cells from
// shared. Phase 3: staged coalesced writeout. DRAM visit factor 1.59x.
__global__ __launch_bounds__(256)
void gather_k(float* __restrict__ out) {
    __shared__ union {
        struct {
            uint2 rows[CAP][32];    // 24576B: fp16 plane-rows (lane l = planes 4l..4l+3)
            int4  meta[CAP];        // 1536B
        } p;
        float acc[TCX * TCY][NPLANE + 4];  // 16896B writeout staging
    } u;
    __shared__ int sGBeg[3], sCnt[3], sBase[3], sBuf[4];

    int tid = threadIdx.x;
    int lane = tid & 31, wid = tid >> 5;            // 8 warps
    int cx0 = (blockIdx.x % TILES_X) * TCX;
    int cy0 = (blockIdx.x / TILES_X) * TCY;
    int xs = max(cx0 - 1, 0);
    int xe = min(cx0 + TCX - 1, WOo - 2);           // anchors exist in [0,1022]

    // phase 0: the 3 contributor anchor-rows' ranges
    if (tid < 3) {
        int ay = cy0 - 1 + tid;
        int gb = 0, cnt = 0, base = 0;
        if (ay >= 0 && ay <= HOo - 2) {             // anchor rows in [0,510]
            int rb = ay << 10;
            base = __ldg(&g_bbase[ay]);
            int o0 = __ldg(&g_off[rb + xs]);
            int o1 = __ldg(&g_off[rb + xe + 1]);
            gb = o0 + base;
            cnt = o1 - o0;
        }
        sGBeg[tid] = gb; sCnt[tid] = cnt; sBase[tid] = base;
    }
    __syncthreads();
    if (tid == 0) {
        sBuf[0] = 0;
        sBuf[1] = sCnt[0];
        sBuf[2] = sCnt[0] + sCnt[1];
        sBuf[3] = sCnt[0] + sCnt[1] + sCnt[2];
    }
    __syncthreads();
    int Tc = min(sBuf[3], CAP);

    // phase 1a: stage entry metas (one global round-trip)
    if (tid < Tc) {
        int j = (tid >= sBuf[1]) + (tid >= sBuf[2]);
        int gi = sGBeg[j] + (tid - sBuf[j]);
        u.p.meta[tid] = __ldg(&g_entry[gi]);
    }
    __syncthreads();
    // phase 1b: stage rows (coalesced 256B per entry, ~12 indep loads/thread)
    for (int i = tid; i < Tc * 32; i += 256) {
        int t = i >> 5, l = i & 31;
        int pix = u.p.meta[t].y;
        u.p.rows[t][l] = __ldg(reinterpret_cast<const uint2*>(
            &g_xt[(size_t)pix * NPLANE + l * 4]));
    }
    __syncthreads();

    // phase 2: warp owns 4 cells in one cell-row
    int cyw = cy0 + (wid >> 2);                     // cell row
    int cx0w = cx0 + (wid & 3) * 4;                 // first cell x
    float a[4][4];
    #pragma unroll
    for (int j = 0; j < 4; j++)
        #pragma unroll
        for (int r = 0; r < 4; r++) a[j][r] = 0.0f;

    int xsw = max(cx0w - 1, 0);
    int xew = min(cx0w + 3, WOo - 2);

    #pragma unroll
    for (int rr = 0; rr < 2; rr++) {
        int ay = cyw - 1 + rr;                      // rr=0: weight wy; rr=1: 1-wy
        if (ay < 0 || ay > HOo - 2) continue;
        int j = ay - (cy0 - 1);                     // buffered row index 0..2
        int rb = ay << 10;
        int gb = __ldg(&g_off[rb + xsw]) + sBase[j];
        int ge = __ldg(&g_off[rb + xew + 1]) + sBase[j];
        int bufb = sBuf[j] + (gb - sGBeg[j]);
        int n = ge - gb;
        #pragma unroll 1
        for (int k = 0; k < n; k++) {
            int pb = bufb + k;
            int4 m; uint2 rv;
            if (pb < Tc) {
                m = u.p.meta[pb];                   // LDS broadcast
                rv = u.p.rows[pb][lane];            // conflict-free LDS.64
            } else {                                // ~never: overflow fallback
                m = __ldg(&g_entry[gb + k]);
                rv = __ldg(reinterpret_cast<const uint2*>(
                    &g_xt[(size_t)m.y * NPLANE + lane * 4]));
            }
            float wx = __int_as_float(m.z);
            float wyr = __int_as_float(m.w);
            float wyv = (rr == 0) ? wyr : (1.0f - wyr);
            float omx = 1.0f - wx;
            float2 f0 = __half22float2(*reinterpret_cast<__half2*>(&rv.x));
            float2 f1 = __half22float2(*reinterpret_cast<__half2*>(&rv.y));
            int d = m.x - cx0w;                     // -1 .. 3
            #pragma unroll
            for (int jj = 0; jj < 4; jj++) {
                float wsel = (d == jj) ? omx : ((d == jj - 1) ? wx : 0.0f);
                float t2 = wsel * wyv;
                a[jj][0] = fmaf(t2, f0.x, a[jj][0]);
                a[jj][1] = fmaf(t2, f0.y, a[jj][1]);
                a[jj][2] = fmaf(t2, f1.x, a[jj][2]);
                a[jj][3] = fmaf(t2, f1.y, a[jj][3]);
            }
        }
    }
    __syncthreads();                                // all reads of u.p done

    // phase 3: stage accumulators (aligned float4 STS), coalesced writeout
    {
        int ry = wid >> 2;
        #pragma unroll
        for (int jj = 0; jj < 4; jj++) {
            int ci = ry * TCX + (wid & 3) * 4 + jj;
            *reinterpret_cast<float4*>(&u.acc[ci][lane * 4]) =
                make_float4(a[jj][0], a[jj][1], a[jj][2], a[jj][3]);
        }
    }
    __syncthreads();
    for (int idx = tid; idx < TCX * TCY * NPLANE; idx += 256) {
        int plane = idx >> 5;
        int c = idx & 31;
        int ryy = c >> 4, cxx = c & 15;
        out[(size_t)plane * NOUT + (cy0 + ryy) * WOo + cx0 + cxx] = u.acc[c][plane];
    }
}

// ---------------------------------------------------------------
extern "C" void kernel_launch(void* const* d_in, const int* in_sizes, int n_in,
                              void* d_out, int out_size) {
    const float*  x    = (const float*)d_in[0];
    const float2* smap = (const float2*)d_in[1];
    float*        out  = (float*)d_out;

    clear_k<<<NOUT / 256, 256>>>();
    {
        dim3 b(32, 8);
        dim3 g(NPIX / 32, NPLANE / 32);
        transpose_k<<<g, b>>>(x);
    }
    hist_k<<<NPIX / 256, 256>>>(smap);
    scanA_k<<<512, 1024>>>();
    scanB_k<<<1, 512>>>();
    scatter_k<<<NPIX / 256, 256>>>(smap);
    gather_k<<<(HOo / TCY) * TILES_X, 256>>>(out);
}

// round 10
// speedup vs baseline: 1.3141x; 1.3141x over previous
#include <cuda_runtime.h>
#include <cuda_fp16.h>

// Problem constants (fixed by the dataset)
#define HH   512
#define WW   1024
#define HOo  512
#define WOo  1024
#define NPIX (HH * WW)          // 524288 input pixels
#define NOUT (HOo * WOo)        // 524288 output cells per plane
#define NPLANE 128              // B*C
#define CPW  4                  // cells per warp (consecutive in x)
#define CELLS_PB 32             // cells per block (one row segment)
#define ROWSLAB 2048            // fixed entry slab per output row (mean ~1024, max ~1150)

// ---- static device scratch ----
__device__ __half g_xt[(size_t)NPIX * NPLANE]; // 128MB transposed x [pixel][plane], fp16
__device__ int    g_count[NOUT];               // zero at start; scanA re-zeroes each run
__device__ int    g_off[NOUT];                 // row-local exclusive scan
__device__ int    g_cursor[NOUT];
__device__ int4   g_entry[512 * ROWSLAB];      // 16MB slab-allocated entries

// ---------------------------------------------------------------
// K1: fused transpose + histogram.
// Block = 64 pixels x all 128 planes. Writeout: warp per pixel, lane l
// stores planes 4l..4l+3 as one uint2 -> full 256B row in ONE wavefront.
__global__ __launch_bounds__(256)
void txh_k(const float* __restrict__ x, const float2* __restrict__ smap) {
    __shared__ __half hbuf[64][132];            // stride 132: uint2-aligned, low conflict
    int p0 = blockIdx.x * 64;
    int tid = threadIdx.x;

    // histogram for this block's 64 pixels (anchors always in-bounds)
    if (tid < 64) {
        float2 s = __ldg(&smap[p0 + tid]);
        int x0 = (int)floorf(s.x);
        int y0 = (int)floorf(s.y);
        atomicAdd(&g_count[(y0 << 10) + x0], 1);
    }

    // load fp32, convert, stage transposed
    #pragma unroll
    for (int it = 0; it < 32; it++) {
        int idx = tid + it * 256;               // 0..8191
        int c  = idx >> 6;                      // plane 0..127
        int px = idx & 63;
        hbuf[px][c] = __float2half(__ldg(&x[(size_t)c * NPIX + p0 + px]));
    }
    __syncthreads();

    // store: one warp per pixel, full 256B row per wavefront
    int lane = tid & 31, wid = tid >> 5;
    #pragma unroll
    for (int i = wid; i < 64; i += 8) {
        uint2 v = *reinterpret_cast<uint2*>(&hbuf[i][lane * 4]);
        *reinterpret_cast<uint2*>(&g_xt[(size_t)(p0 + i) * NPLANE + lane * 4]) = v;
    }
}

// K2: per-row (1024 cells) exclusive scan -> row-local offsets + cursors.
// Also zeroes g_count for the next graph replay (self-cleaning).
__global__ __launch_bounds__(1024)
void scanA_k() {
    int tid = threadIdx.x;
    int cell = blockIdx.x * 1024 + tid;         // blockIdx.x = output row y
    int cnt = g_count[cell];
    g_count[cell] = 0;                          // ready for next replay
    int lane = tid & 31, wid = tid >> 5;
    int v = cnt;
    #pragma unroll
    for (int d = 1; d < 32; d <<= 1) {
        int t = __shfl_up_sync(0xFFFFFFFFu, v, d);
        if (lane >= d) v += t;
    }
    __shared__ int wsum[32];
    if (lane == 31) wsum[wid] = v;
    __syncthreads();
    if (wid == 0) {
        int s = wsum[lane];
        #pragma unroll
        for (int d = 1; d < 32; d <<= 1) {
            int t = __shfl_up_sync(0xFFFFFFFFu, s, d);
            if (lane >= d) s += t;
        }
        wsum[lane] = s;
    }
    __syncthreads();
    int excl = v - cnt + (wid ? wsum[wid - 1] : 0);
    g_off[cell] = excl;
    g_cursor[cell] = excl;
}

// K3: scatter one entry per pixel into its row slab
__global__ __launch_bounds__(256)
void scatter_k(const float2* __restrict__ smap) {
    int p = blockIdx.x * blockDim.x + threadIdx.x;
    if (p >= NPIX) return;
    float2 s = __ldg(&smap[p]);
    float x0f = floorf(s.x), y0f = floorf(s.y);
    int x0 = (int)x0f, y0 = (int)y0f;
    float wx = s.x - x0f, wy = s.y - y0f;
    int pos = atomicAdd(&g_cursor[(y0 << 10) + x0], 1) + (y0 << 11);
    g_entry[pos] = make_int4(x0, p, __float_as_int(wx), __float_as_int(wy));
}

// K4: gather (R7 structure — best measured). Warp owns CPW cells x 128
// planes in registers; merged index space over both contributor rows;
// uniform 4-wide chunks with one-chunk prefetch. Slab entry addressing.
__global__ __launch_bounds__(256)
void gather_k(float* __restrict__ out) {
    __shared__ float acc_s[CELLS_PB][NPLANE + 1];
    int tid = threadIdx.x;
    int lane = tid & 31, wid = tid >> 5;            // 8 warps
    int cell0 = blockIdx.x * CELLS_PB;              // 32-aligned -> one row
    int cy = cell0 >> 10;
    int cx0 = (cell0 & 1023) + wid * CPW;

    float a[CPW][4];
    #pragma unroll
    for (int j = 0; j < CPW; j++)
        #pragma unroll
        for (int r = 0; r < 4; r++) a[j][r] = 0.0f;

    int xs = max(cx0 - 1, 0);
    int xe = min(cx0 + CPW - 1, WOo - 2);           // anchors exist in [0,1022]

    // contributor ranges: anchor rows cy-1 (weight wy) and cy (weight 1-wy)
    int beg0 = 0, cnt0 = 0, beg1 = 0, cnt1 = 0;
    if (cy >= 1) {
        int rb = (cy - 1) << 10;
        int o0 = __ldg(&g_off[rb + xs]);
        beg0 = o0 + ((cy - 1) << 11);
        cnt0 = __ldg(&g_off[rb + xe + 1]) - o0;
    }
    if (cy <= HOo - 2) {
        int rb = cy << 10;
        int o0 = __ldg(&g_off[rb + xs]);
        beg1 = o0 + (cy << 11);
        cnt1 = __ldg(&g_off[rb + xe + 1]) - o0;
    }
    int total = cnt0 + cnt1;

    auto eload = [&](int k) {
        int kc = min(k, total - 1);
        bool r0 = kc < cnt0;
        int idx = r0 ? (beg0 + kc) : (beg1 + kc - cnt0);
        int4 e = __ldg(&g_entry[idx]);
        float wy = __int_as_float(e.w);
        float wyv = r0 ? wy : (1.0f - wy);
        e.w = __float_as_int((k < total) ? wyv : 0.0f);
        return e;
    };
    auto ldrow = [&](int4 e) {
        return __ldg(reinterpret_cast<const uint2*>(
            &g_xt[(size_t)e.y * NPLANE + lane * 4]));
    };
    auto process = [&](int4 e, uint2 r) {
        float wx = __int_as_float(e.z);
        float wyv = __int_as_float(e.w);
        float omx = 1.0f - wx;
        float2 f0 = __half22float2(*reinterpret_cast<__half2*>(&r.x));
        float2 f1 = __half22float2(*reinterpret_cast<__half2*>(&r.y));
        int d = e.x - cx0;                          // -1 .. CPW-1
        #pragma unroll
        for (int j = 0; j < CPW; j++) {
            float wsel = (d == j) ? omx : ((d == j - 1) ? wx : 0.0f);
            float t = wsel * wyv;
            a[j][0] = fmaf(t, f0.x, a[j][0]);
            a[j][1] = fmaf(t, f0.y, a[j][1]);
            a[j][2] = fmaf(t, f1.x, a[j][2]);
            a[j][3] = fmaf(t, f1.y, a[j][3]);
        }
    };

    if (total > 0) {
        int4 E0[4]; uint2 R0[4];
        #pragma unroll
        for (int j = 0; j < 4; j++) E0[j] = eload(j);
        #pragma unroll
        for (int j = 0; j < 4; j++) R0[j] = ldrow(E0[j]);

        #pragma unroll 1
        for (int base = 0; base < total; base += 4) {
            int4 E1[4]; uint2 R1[4];
            if (base + 4 < total) {                 // prefetch next chunk
                #pragma unroll
                for (int j = 0; j < 4; j++) E1[j] = eload(base + 4 + j);
                #pragma unroll
                for (int j = 0; j < 4; j++) R1[j] = ldrow(E1[j]);
            }
            #pragma unroll
            for (int j = 0; j < 4; j++) process(E0[j], R0[j]);
            #pragma unroll
            for (int j = 0; j < 4; j++) { E0[j] = E1[j]; R0[j] = R1[j]; }
        }
    }

    // stage to shared (plane = lane*4 + r), then coalesced writeout
    #pragma unroll
    for (int j = 0; j < CPW; j++) {
        int ci = wid * CPW + j;
        acc_s[ci][lane * 4 + 0] = a[j][0];
        acc_s[ci][lane * 4 + 1] = a[j][1];
        acc_s[ci][lane * 4 + 2] = a[j][2];
        acc_s[ci][lane * 4 + 3] = a[j][3];
    }
    __syncthreads();

    for (int idx = tid; idx < CELLS_PB * NPLANE; idx += 256) {
        int plane = idx >> 5;
        int ci = idx & (CELLS_PB - 1);
        out[(size_t)plane * NOUT + cell0 + ci] = acc_s[ci][plane];
    }
}

// ---------------------------------------------------------------
extern "C" void kernel_launch(void* const* d_in, const int* in_sizes, int n_in,
                              void* d_out, int out_size) {
    const float*  x    = (const float*)d_in[0];
    const float2* smap = (const float2*)d_in[1];
    float*        out  = (float*)d_out;

    txh_k<<<NPIX / 64, 256>>>(x, smap);
    scanA_k<<<512, 1024>>>();
    scatter_k<<<NPIX / 256, 256>>>(smap);
    gather_k<<<NOUT / CELLS_PB, 256>>>(out);
}

// round 12
// speedup vs baseline: 1.3288x; 1.0111x over previous
#include <cuda_runtime.h>
#include <cuda_fp16.h>

// Problem constants (fixed by the dataset)
#define HH   512
#define WW   1024
#define HOo  512
#define WOo  1024
#define NPIX (HH * WW)          // 524288 input pixels
#define NOUT (HOo * WOo)        // 524288 output cells per plane
#define NPLANE 128              // B*C
#define CPW  2                  // cells per warp (consecutive in x)
#define CELLS_PB 16             // 8 warps x 2 cells per block (one row segment)
#define ROWSLAB 2048            // fixed entry slab per output row (mean ~1024, max ~1150)

// ---- static device scratch ----
__device__ __half g_xt[(size_t)NPIX * NPLANE]; // 128MB transposed x [pixel][plane], fp16
__device__ int    g_count[NOUT];               // zero at start; scanA re-zeroes each run
__device__ int    g_off[NOUT];                 // row-local exclusive scan
__device__ int    g_cursor[NOUT];
__device__ int4   g_entry[512 * ROWSLAB];      // 16MB slab-allocated entries

// ---------------------------------------------------------------
// K1: fused transpose + histogram.
// Block = 64 pixels x all 128 planes. Writeout: warp per pixel, lane l
// stores planes 4l..4l+3 as one uint2 -> full 256B row in ONE wavefront.
__global__ __launch_bounds__(256)
void txh_k(const float* __restrict__ x, const float2* __restrict__ smap) {
    __shared__ __half hbuf[64][132];            // stride 132: uint2-aligned, low conflict
    int p0 = blockIdx.x * 64;
    int tid = threadIdx.x;

    // histogram for this block's 64 pixels (anchors always in-bounds)
    if (tid < 64) {
        float2 s = __ldg(&smap[p0 + tid]);
        int x0 = (int)floorf(s.x);
        int y0 = (int)floorf(s.y);
        atomicAdd(&g_count[(y0 << 10) + x0], 1);
    }

    // load fp32, convert, stage transposed
    #pragma unroll
    for (int it = 0; it < 32; it++) {
        int idx = tid + it * 256;               // 0..8191
        int c  = idx >> 6;                      // plane 0..127
        int px = idx & 63;
        hbuf[px][c] = __float2half(__ldg(&x[(size_t)c * NPIX + p0 + px]));
    }
    __syncthreads();

    // store: one warp per pixel, full 256B row per wavefront
    int lane = tid & 31, wid = tid >> 5;
    #pragma unroll
    for (int i = wid; i < 64; i += 8) {
        uint2 v = *reinterpret_cast<uint2*>(&hbuf[i][lane * 4]);
        *reinterpret_cast<uint2*>(&g_xt[(size_t)(p0 + i) * NPLANE + lane * 4]) = v;
    }
}

// K2: per-row (1024 cells) exclusive scan -> row-local offsets + cursors.
// Also zeroes g_count for the next graph replay (self-cleaning).
__global__ __launch_bounds__(1024)
void scanA_k() {
    int tid = threadIdx.x;
    int cell = blockIdx.x * 1024 + tid;         // blockIdx.x = output row y
    int cnt = g_count[cell];
    g_count[cell] = 0;                          // ready for next replay
    int lane = tid & 31, wid = tid >> 5;
    int v = cnt;
    #pragma unroll
    for (int d = 1; d < 32; d <<= 1) {
        int t = __shfl_up_sync(0xFFFFFFFFu, v, d);
        if (lane >= d) v += t;
    }
    __shared__ int wsum[32];
    if (lane == 31) wsum[wid] = v;
    __syncthreads();
    if (wid == 0) {
        int s = wsum[lane];
        #pragma unroll
        for (int d = 1; d < 32; d <<= 1) {
            int t = __shfl_up_sync(0xFFFFFFFFu, s, d);
            if (lane >= d) s += t;
        }
        wsum[lane] = s;
    }
    __syncthreads();
    int excl = v - cnt + (wid ? wsum[wid - 1] : 0);
    g_off[cell] = excl;
    g_cursor[cell] = excl;
}

// K3: scatter one entry per pixel into its row slab
__global__ __launch_bounds__(256)
void scatter_k(const float2* __restrict__ smap) {
    int p = blockIdx.x * blockDim.x + threadIdx.x;
    if (p >= NPIX) return;
    float2 s = __ldg(&smap[p]);
    float x0f = floorf(s.x), y0f = floorf(s.y);
    int x0 = (int)x0f, y0 = (int)y0f;
    float wx = s.x - x0f, wy = s.y - y0f;
    int pos = atomicAdd(&g_cursor[(y0 << 10) + x0], 1) + (y0 << 11);
    g_entry[pos] = make_int4(x0, p, __float_as_int(wx), __float_as_int(wy));
}

// K4: gather. Issue-bound -> minimize per-entry ops and registers:
// warp owns 2 cells x 128 planes (8 accumulator regs), plain 2-row loops,
// no prefetch buffers (occupancy hides latency). d in {-1,0,1} -> 4 selects
// + 8 FMA per entry.
__global__ __launch_bounds__(256)
void gather_k(float* __restrict__ out) {
    // NPLANE+4 pad: row stride 132 floats = 528B, divisible by 16 ->
    // float4 staging stores stay aligned for every cell index.
    __shared__ float acc_s[CELLS_PB][NPLANE + 4];
    int tid = threadIdx.x;
    int lane = tid & 31, wid = tid >> 5;            // 8 warps
    int cell0 = blockIdx.x * CELLS_PB;              // 16-aligned -> one row
    int cy = cell0 >> 10;
    int cx0 = (cell0 & 1023) + wid * CPW;

    float a0[4] = {0.f, 0.f, 0.f, 0.f};             // cell cx0
    float a1[4] = {0.f, 0.f, 0.f, 0.f};             // cell cx0+1

    int xs = max(cx0 - 1, 0);
    int xe = min(cx0 + CPW - 1, WOo - 2);           // anchors exist in [0,1022]

    #pragma unroll
    for (int rr = 0; rr < 2; rr++) {
        int ay = cy - 1 + rr;                       // rr=0: weight wy; rr=1: 1-wy
        if ((unsigned)ay > (unsigned)(HOo - 2)) continue;
        int rb = ay << 10;
        int o0 = __ldg(&g_off[rb + xs]);
        int o1 = __ldg(&g_off[rb + xe + 1]);
        int beg = o0 + (ay << 11);
        int end = o1 + (ay << 11);

        #pragma unroll 2
        for (int i = beg; i < end; i++) {
            int4 e = __ldg(&g_entry[i]);
            uint2 r = __ldg(reinterpret_cast<const uint2*>(
                &g_xt[(size_t)e.y * NPLANE + lane * 4]));
            float wx = __int_as_float(e.z);
            float wyr = __int_as_float(e.w);
            float wyv = rr ? (1.0f - wyr) : wyr;
            float omx = 1.0f - wx;
            int d = e.x - cx0;                      // -1, 0, 1
            float w0 = (d == 0) ? omx : ((d == -1) ? wx : 0.0f);
            float w1 = (d == 1) ? omx : ((d == 0) ? wx : 0.0f);
            w0 *= wyv;
            w1 *= wyv;
            float2 f0 = __half22float2(*reinterpret_cast<__half2*>(&r.x));
            float2 f1 = __half22float2(*reinterpret_cast<__half2*>(&r.y));
            a0[0] = fmaf(w0, f0.x, a0[0]);
            a0[1] = fmaf(w0, f0.y, a0[1]);
            a0[2] = fmaf(w0, f1.x, a0[2]);
            a0[3] = fmaf(w0, f1.y, a0[3]);
            a1[0] = fmaf(w1, f0.x, a1[0]);
            a1[1] = fmaf(w1, f0.y, a1[1]);
            a1[2] = fmaf(w1, f1.x, a1[2]);
            a1[3] = fmaf(w1, f1.y, a1[3]);
        }
    }

    // stage to shared (plane = lane*4 + r), then coalesced writeout
    {
        int ci = wid * CPW;
        *reinterpret_cast<float4*>(&acc_s[ci][lane * 4]) =
            make_float4(a0[0], a0[1], a0[2], a0[3]);
        *reinterpret_cast<float4*>(&acc_s[ci + 1][lane * 4]) =
            make_float4(a1[0], a1[1], a1[2], a1[3]);
    }
    __syncthreads();

    for (int idx = tid; idx < CELLS_PB * NPLANE; idx += 256) {
        int plane = idx >> 4;                       // 16 cells per segment
        int ci = idx & (CELLS_PB - 1);
        out[(size_t)plane * NOUT + cell0 + ci] = acc_s[ci][plane];
    }
}

// ---------------------------------------------------------------
extern "C" void kernel_launch(void* const* d_in, const int* in_sizes, int n_in,
                              void* d_out, int out_size) {
    const float*  x    = (const float*)d_in[0];
    const float2* smap = (const float2*)d_in[1];
    float*        out  = (float*)d_out;

    txh_k<<<NPIX / 64, 256>>>(x, smap);
    scanA_k<<<512, 1024>>>();
    scatter_k<<<NPIX / 256, 256>>>(smap);
    gather_k<<<NOUT / CELLS_PB, 256>>>(out);
}